// round 17
// baseline (speedup 1.0000x reference)
#include <cuda_runtime.h>
#include <cuda_fp16.h>
#include <math.h>

#define T_SEQ   4096
#define B_BATCH 4
#define C_EMB   1024
#define H_DIM   64
#define NROWS   (B_BATCH * T_SEQ)   // 16384
#define QB_CNT  (T_SEQ / 64)        // 64 query blocks per batch
#define MAXCH   16                  // 256-key chunks per q-block
#define KSPLIT  4                   // proj k-splits (256 k each)

__device__ float g_Q[NROWS * H_DIM];
__device__ float g_K[NROWS * H_DIM];
__device__ float g_V[NROWS * H_DIM];
// split-K partials: O in fp16 ([b][qb][chunk][64 rows][32 half2]), m/l fp32
__device__ __half2 g_Oph[(size_t)B_BATCH * QB_CNT * MAXCH * 64 * 32];
__device__ float   g_ml[(size_t)B_BATCH * QB_CNT * MAXCH * 64 * 2];
__device__ int     g_cnt[B_BATCH * QB_CNT];

// ---- helpers -------------------------------------------------------------
__device__ __forceinline__ unsigned h2u(float a, float b) {
    __half2 h = __floats2half2_rn(a, b);
    return *(unsigned*)&h;
}
__device__ __forceinline__ void mma_f16(float* d, const unsigned* a,
                                        unsigned b0, unsigned b1) {
    asm("mma.sync.aligned.m16n8k16.row.col.f32.f16.f16.f32 "
        "{%0,%1,%2,%3}, {%4,%5,%6,%7}, {%8,%9}, {%0,%1,%2,%3};"
        : "+f"(d[0]), "+f"(d[1]), "+f"(d[2]), "+f"(d[3])
        : "r"(a[0]), "r"(a[1]), "r"(a[2]), "r"(a[3]), "r"(b0), "r"(b1));
}
__device__ __forceinline__ unsigned ldu32(const __half* p) {
    return *(const unsigned*)p;
}

// ---------------------------------------------------------------------------
// Kernel 0: zero Q/K/V accumulators and combine counters.
// ---------------------------------------------------------------------------
__global__ __launch_bounds__(256) void zero_qkv()
{
    size_t i = (size_t)blockIdx.x * blockDim.x + threadIdx.x;
    float4 z = make_float4(0.f, 0.f, 0.f, 0.f);
    ((float4*)g_Q)[i] = z;
    ((float4*)g_K)[i] = z;
    ((float4*)g_V)[i] = z;
    if (blockIdx.x == 0 && threadIdx.x < B_BATCH * QB_CNT)
        g_cnt[threadIdx.x] = 0;
}

// ---------------------------------------------------------------------------
// Kernel 1: QKV projection, split-K, fp16 MMA (unchanged from R15).
// ---------------------------------------------------------------------------
__global__ __launch_bounds__(256) void proj_kernel(
    const float* __restrict__ x,
    const float* __restrict__ Wq,
    const float* __restrict__ Wk,
    const float* __restrict__ Wv)
{
    const float* W;
    float* outp;
    if (blockIdx.z == 0)      { W = Wq; outp = g_Q; }
    else if (blockIdx.z == 1) { W = Wk; outp = g_K; }
    else                      { W = Wv; outp = g_V; }

    __shared__ __half Xs[128][40];   // [row][k 0..31]
    __shared__ __half Wt[64][40];    // [n][k 0..31]  (transposed)

    const int tid  = threadIdx.x;
    const int warp = tid >> 5;
    const int lane = tid & 31;
    const int g  = lane >> 2;
    const int tg = lane & 3;
    const int row0  = blockIdx.x * 128;
    const int kbase = blockIdx.y * (C_EMB / KSPLIT);

    float acc[8][4];
#pragma unroll
    for (int a = 0; a < 8; a++)
#pragma unroll
        for (int j = 0; j < 4; j++) acc[a][j] = 0.0f;

    float4 px[4], pw[2];
#pragma unroll
    for (int s = 0; s < 4; s++) {
        int idx = tid + s * 256, r = idx >> 3, c4 = idx & 7;
        px[s] = *(const float4*)(x + (size_t)(row0 + r) * C_EMB + kbase + c4 * 4);
    }
#pragma unroll
    for (int s = 0; s < 2; s++) {
        int idx = tid + s * 256, r = idx >> 4, c4 = idx & 15;
        pw[s] = *(const float4*)(W + (size_t)(kbase + r) * H_DIM + c4 * 4);
    }

    for (int c = 0; c < C_EMB / KSPLIT / 32; c++) {
#pragma unroll
        for (int s = 0; s < 4; s++) {
            int idx = tid + s * 256, r = idx >> 3, c4 = idx & 7;
            uint2 v = make_uint2(h2u(px[s].x, px[s].y), h2u(px[s].z, px[s].w));
            *(uint2*)&Xs[r][c4 * 4] = v;
        }
#pragma unroll
        for (int s = 0; s < 2; s++) {
            int idx = tid + s * 256, r = idx >> 4, c4 = idx & 15;
            Wt[c4 * 4 + 0][r] = __float2half_rn(pw[s].x);
            Wt[c4 * 4 + 1][r] = __float2half_rn(pw[s].y);
            Wt[c4 * 4 + 2][r] = __float2half_rn(pw[s].z);
            Wt[c4 * 4 + 3][r] = __float2half_rn(pw[s].w);
        }
        __syncthreads();

        if (c + 1 < C_EMB / KSPLIT / 32) {
            int k0 = kbase + (c + 1) * 32;
#pragma unroll
            for (int s = 0; s < 4; s++) {
                int idx = tid + s * 256, r = idx >> 3, c4 = idx & 7;
                px[s] = *(const float4*)(x + (size_t)(row0 + r) * C_EMB + k0 + c4 * 4);
            }
#pragma unroll
            for (int s = 0; s < 2; s++) {
                int idx = tid + s * 256, r = idx >> 4, c4 = idx & 15;
                pw[s] = *(const float4*)(W + (size_t)(k0 + r) * H_DIM + c4 * 4);
            }
        }

#pragma unroll
        for (int kc = 0; kc < 32; kc += 16) {
            unsigned a[4];
            a[0] = ldu32(&Xs[warp * 16 + g    ][kc + 2 * tg    ]);
            a[1] = ldu32(&Xs[warp * 16 + g + 8][kc + 2 * tg    ]);
            a[2] = ldu32(&Xs[warp * 16 + g    ][kc + 2 * tg + 8]);
            a[3] = ldu32(&Xs[warp * 16 + g + 8][kc + 2 * tg + 8]);
#pragma unroll
            for (int at = 0; at < 8; at++) {
                unsigned b0 = ldu32(&Wt[at * 8 + g][kc + 2 * tg    ]);
                unsigned b1 = ldu32(&Wt[at * 8 + g][kc + 2 * tg + 8]);
                mma_f16(acc[at], a, b0, b1);
            }
        }
        __syncthreads();
    }

    const int r0 = row0 + warp * 16 + g;
#pragma unroll
    for (int at = 0; at < 8; at++) {
        int cc = at * 8 + tg * 2;
        atomicAdd(&outp[(size_t)r0 * H_DIM + cc],           acc[at][0]);
        atomicAdd(&outp[(size_t)r0 * H_DIM + cc + 1],       acc[at][1]);
        atomicAdd(&outp[(size_t)(r0 + 8) * H_DIM + cc],     acc[at][2]);
        atomicAdd(&outp[(size_t)(r0 + 8) * H_DIM + cc + 1], acc[at][3]);
    }
}

// ---------------------------------------------------------------------------
// Kernel 2: split-K flash partial + fused last-CTA combine.
// ---------------------------------------------------------------------------
__global__ __launch_bounds__(128, 3) void flash_part_kernel(float* __restrict__ out)
{
    const int chunk = blockIdx.x;
    const int qb    = (QB_CNT - 1) - blockIdx.y;   // heavy blocks first
    const int b     = blockIdx.z;
    if (chunk * 4 > qb) return;                    // beyond causal limit

    const int row0 = qb * 64;
    const int nkt  = min(4, qb + 1 - chunk * 4);   // 64-key tiles (exact)
    const int nc   = qb / 4 + 1;                   // active chunks for this qb

    const float* Qp = g_Q + (size_t)b * T_SEQ * H_DIM;
    const float* Kp = g_K + (size_t)b * T_SEQ * H_DIM;
    const float* Vp = g_V + (size_t)b * T_SEQ * H_DIM;

    __shared__ __half Ks[2][64][72];   // [key][ch]; also Q staging
    __shared__ __half Vt[2][64][74];   // [h][key]  pitch 74
    __shared__ __half Ps[64][72];      // [row][key]
    __shared__ int    sIsLast;

    const int tid  = threadIdx.x;
    const int warp = tid >> 5;
    const int lane = tid & 31;
    const int g  = lane >> 2;
    const int tg = lane & 3;

    // ---- stage Q through Ks flat, extract a-frags ----
    {
        __half* Qs = (__half*)Ks;
        for (int i = tid; i < 1024; i += 128) {
            int r = i >> 4, c4 = i & 15;
            float4 v = *(const float4*)(Qp + (size_t)(row0 + r) * H_DIM + c4 * 4);
            *(uint2*)&Qs[r * 72 + c4 * 4] =
                make_uint2(h2u(v.x, v.y), h2u(v.z, v.w));
        }
    }
    __syncthreads();

    unsigned qa[4][4];
    {
        const __half* Qs = (const __half*)Ks;
        const int r0 = warp * 16 + g, r1 = r0 + 8;
#pragma unroll
        for (int kc4 = 0; kc4 < 4; kc4++) {
            int kc = kc4 * 16;
            qa[kc4][0] = ldu32(&Qs[r0 * 72 + kc + 2 * tg    ]);
            qa[kc4][1] = ldu32(&Qs[r1 * 72 + kc + 2 * tg    ]);
            qa[kc4][2] = ldu32(&Qs[r0 * 72 + kc + 2 * tg + 8]);
            qa[kc4][3] = ldu32(&Qs[r1 * 72 + kc + 2 * tg + 8]);
        }
    }
    __syncthreads();

    float o[8][4];
#pragma unroll
    for (int a = 0; a < 8; a++)
#pragma unroll
        for (int j = 0; j < 4; j++) o[a][j] = 0.0f;
    float m0 = -1e30f, m1 = -1e30f, l0 = 0.0f, l1 = 0.0f;

    const int r0g = row0 + warp * 16 + g;
    const int r1g = r0g + 8;

    const int ld_r  = tid >> 4;          // 0..7
    const int ld_c4 = tid & 15;          // 0..15

    // ---- preload tile 0 (64 keys) into stage 0 ----
    {
        const int key0 = chunk * 256;
        float4 t;
#pragma unroll
        for (int s = 0; s < 8; s++) {
            int r = ld_r + s * 8;
            t = *(const float4*)(Kp + (size_t)(key0 + r) * H_DIM + ld_c4 * 4);
            *(uint2*)&Ks[0][r][ld_c4 * 4] = make_uint2(h2u(t.x, t.y), h2u(t.z, t.w));
        }
#pragma unroll
        for (int s = 0; s < 8; s++) {
            int r = ld_r + s * 8;
            t = *(const float4*)(Vp + (size_t)(key0 + r) * H_DIM + ld_c4 * 4);
            Vt[0][ld_c4 * 4 + 0][r] = __float2half_rn(t.x);
            Vt[0][ld_c4 * 4 + 1][r] = __float2half_rn(t.y);
            Vt[0][ld_c4 * 4 + 2][r] = __float2half_rn(t.z);
            Vt[0][ld_c4 * 4 + 3][r] = __float2half_rn(t.w);
        }
    }

    for (int kb = 0; kb < nkt; kb++) {
        const int cur  = kb & 1;
        const int nxt  = 1 - cur;
        const int key0 = chunk * 256 + kb * 64;
        const bool more = (kb + 1 < nkt);
        __syncthreads();

        float4 pk[8];
        if (more) {
            const int keyn = key0 + 64;
#pragma unroll
            for (int s = 0; s < 8; s++) {
                int r = ld_r + s * 8;
                pk[s] = *(const float4*)(Kp + (size_t)(keyn + r) * H_DIM + ld_c4 * 4);
            }
        }

        // ---- S = Q K^T ----
        float s[8][4];
#pragma unroll
        for (int a = 0; a < 8; a++)
#pragma unroll
            for (int j = 0; j < 4; j++) s[a][j] = 0.0f;

#pragma unroll
        for (int kc4 = 0; kc4 < 4; kc4++) {
            int kc = kc4 * 16;
#pragma unroll
            for (int at = 0; at < 8; at++) {
                unsigned b0 = ldu32(&Ks[cur][at * 8 + g][kc + 2 * tg    ]);
                unsigned b1 = ldu32(&Ks[cur][at * 8 + g][kc + 2 * tg + 8]);
                mma_f16(s[at], qa[kc4], b0, b1);
            }
        }

        float4 pv[8];
        if (more) {
#pragma unroll
            for (int s2 = 0; s2 < 8; s2++) {
                int r = ld_r + s2 * 8;
                *(uint2*)&Ks[nxt][r][ld_c4 * 4] =
                    make_uint2(h2u(pk[s2].x, pk[s2].y), h2u(pk[s2].z, pk[s2].w));
            }
            const int keyn = key0 + 64;
#pragma unroll
            for (int s2 = 0; s2 < 8; s2++) {
                int r = ld_r + s2 * 8;
                pv[s2] = *(const float4*)(Vp + (size_t)(keyn + r) * H_DIM + ld_c4 * 4);
            }
        }

        // ---- scale + causal mask ----
        const bool diag = (key0 == row0);
#pragma unroll
        for (int at = 0; at < 8; at++) {
            s[at][0] *= 0.125f; s[at][1] *= 0.125f;
            s[at][2] *= 0.125f; s[at][3] *= 0.125f;
            if (diag) {
                int c0 = key0 + at * 8 + tg * 2;
                if (c0     > r0g) s[at][0] = -1e30f;
                if (c0 + 1 > r0g) s[at][1] = -1e30f;
                if (c0     > r1g) s[at][2] = -1e30f;
                if (c0 + 1 > r1g) s[at][3] = -1e30f;
            }
        }

        // ---- online softmax ----
        float tm0 = -1e30f, tm1 = -1e30f;
#pragma unroll
        for (int at = 0; at < 8; at++) {
            tm0 = fmaxf(tm0, fmaxf(s[at][0], s[at][1]));
            tm1 = fmaxf(tm1, fmaxf(s[at][2], s[at][3]));
        }
        tm0 = fmaxf(tm0, __shfl_xor_sync(0xffffffffu, tm0, 1));
        tm0 = fmaxf(tm0, __shfl_xor_sync(0xffffffffu, tm0, 2));
        tm1 = fmaxf(tm1, __shfl_xor_sync(0xffffffffu, tm1, 1));
        tm1 = fmaxf(tm1, __shfl_xor_sync(0xffffffffu, tm1, 2));

        float nm0 = fmaxf(m0, tm0), nm1 = fmaxf(m1, tm1);
        float al0 = __expf(m0 - nm0), al1 = __expf(m1 - nm1);
        m0 = nm0; m1 = nm1;

        float tl0 = 0.0f, tl1 = 0.0f;
#pragma unroll
        for (int at = 0; at < 8; at++) {
            s[at][0] = __expf(s[at][0] - nm0);
            s[at][1] = __expf(s[at][1] - nm0);
            s[at][2] = __expf(s[at][2] - nm1);
            s[at][3] = __expf(s[at][3] - nm1);
            tl0 += s[at][0] + s[at][1];
            tl1 += s[at][2] + s[at][3];
        }
        tl0 += __shfl_xor_sync(0xffffffffu, tl0, 1);
        tl0 += __shfl_xor_sync(0xffffffffu, tl0, 2);
        tl1 += __shfl_xor_sync(0xffffffffu, tl1, 1);
        tl1 += __shfl_xor_sync(0xffffffffu, tl1, 2);
        l0 = l0 * al0 + tl0;
        l1 = l1 * al1 + tl1;

#pragma unroll
        for (int at = 0; at < 8; at++) {
            o[at][0] *= al0; o[at][1] *= al0;
            o[at][2] *= al1; o[at][3] *= al1;
        }

#pragma unroll
        for (int at = 0; at < 8; at++) {
            int c = at * 8 + 2 * tg;
            *(unsigned*)&Ps[warp * 16 + g    ][c] = h2u(s[at][0], s[at][1]);
            *(unsigned*)&Ps[warp * 16 + g + 8][c] = h2u(s[at][2], s[at][3]);
        }
        __syncwarp();

        // ---- O += P V ----
#pragma unroll
        for (int kc = 0; kc < 64; kc += 16) {
            unsigned a[4];
            a[0] = ldu32(&Ps[warp * 16 + g    ][kc + 2 * tg    ]);
            a[1] = ldu32(&Ps[warp * 16 + g + 8][kc + 2 * tg    ]);
            a[2] = ldu32(&Ps[warp * 16 + g    ][kc + 2 * tg + 8]);
            a[3] = ldu32(&Ps[warp * 16 + g + 8][kc + 2 * tg + 8]);
#pragma unroll
            for (int at = 0; at < 8; at++) {
                unsigned b0 = ldu32(&Vt[cur][at * 8 + g][kc + 2 * tg    ]);
                unsigned b1 = ldu32(&Vt[cur][at * 8 + g][kc + 2 * tg + 8]);
                mma_f16(o[at], a, b0, b1);
            }
        }

        if (more) {
#pragma unroll
            for (int s2 = 0; s2 < 8; s2++) {
                int r = ld_r + s2 * 8;
                Vt[nxt][ld_c4 * 4 + 0][r] = __float2half_rn(pv[s2].x);
                Vt[nxt][ld_c4 * 4 + 1][r] = __float2half_rn(pv[s2].y);
                Vt[nxt][ld_c4 * 4 + 2][r] = __float2half_rn(pv[s2].z);
                Vt[nxt][ld_c4 * 4 + 3][r] = __float2half_rn(pv[s2].w);
            }
        }
    }

    // ---- write partial (fp16 O, fp32 m/l) ----
    const size_t pbase = ((size_t)(b * QB_CNT + qb) * MAXCH + chunk);
    __half2* Op = g_Oph + pbase * 64 * 32;
    float* mlp = g_ml + pbase * 64 * 2;

    const int lr0 = warp * 16 + g;
#pragma unroll
    for (int at = 0; at < 8; at++) {
        int ch = (at * 8 + tg * 2) >> 1;
        Op[lr0 * 32 + ch]       = __floats2half2_rn(o[at][0], o[at][1]);
        Op[(lr0 + 8) * 32 + ch] = __floats2half2_rn(o[at][2], o[at][3]);
    }
    if (tg == 0) {
        mlp[lr0 * 2 + 0] = m0;  mlp[lr0 * 2 + 1] = l0;
        mlp[(lr0 + 8) * 2 + 0] = m1;  mlp[(lr0 + 8) * 2 + 1] = l1;
    }

    // ---- last CTA for this (b,qb) combines all partials ----
    __threadfence();
    __syncthreads();
    if (tid == 0) {
        int prev = atomicAdd(&g_cnt[b * QB_CNT + qb], 1);
        sIsLast = (prev == nc - 1);
    }
    __syncthreads();
    if (!sIsLast) return;
    __threadfence();   // acquire: make all chunks' partials visible

    const size_t cbase = (size_t)(b * QB_CNT + qb) * MAXCH;
    const int row = tid >> 1;          // 0..63
    const int seg = tid & 1;           // 0..1 (32 cols each)

    float M = -1e30f;
    for (int c = 0; c < nc; c++)
        M = fmaxf(M, g_ml[(cbase + c) * 128 + row * 2 + 0]);

    float L = 0.0f;
    float acc[32];
#pragma unroll
    for (int j = 0; j < 32; j++) acc[j] = 0.0f;

    for (int c = 0; c < nc; c++) {
        float mm = g_ml[(cbase + c) * 128 + row * 2 + 0];
        float ll = g_ml[(cbase + c) * 128 + row * 2 + 1];
        float w = __expf(mm - M);
        L += w * ll;
        const __half2* Ob = g_Oph + (cbase + c) * 2048 + row * 32 + seg * 16;
#pragma unroll
        for (int j = 0; j < 16; j++) {
            float2 v = __half22float2(Ob[j]);
            acc[j * 2 + 0] += w * v.x;
            acc[j * 2 + 1] += w * v.y;
        }
    }

    float inv = 1.0f / L;
    float* op = out + (size_t)b * T_SEQ * H_DIM +
                (size_t)(row0 + row) * H_DIM + seg * 32;
#pragma unroll
    for (int j4 = 0; j4 < 8; j4++)
        *(float4*)(op + j4 * 4) = make_float4(acc[j4 * 4 + 0] * inv,
                                              acc[j4 * 4 + 1] * inv,
                                              acc[j4 * 4 + 2] * inv,
                                              acc[j4 * 4 + 3] * inv);
}

// ---------------------------------------------------------------------------
extern "C" void kernel_launch(void* const* d_in, const int* in_sizes, int n_in,
                              void* d_out, int out_size)
{
    const float* x  = (const float*)d_in[0];
    const float* Wq = (const float*)d_in[1];
    const float* Wk = (const float*)d_in[2];
    const float* Wv = (const float*)d_in[3];
    float* out = (float*)d_out;

    zero_qkv<<<NROWS * H_DIM / 4 / 256, 256>>>();

    dim3 g1(NROWS / 128, KSPLIT, 3);
    proj_kernel<<<g1, 256>>>(x, Wq, Wk, Wv);

    dim3 g2(MAXCH, QB_CNT, B_BATCH);
    flash_part_kernel<<<g2, 128>>>(out);
}